// round 6
// baseline (speedup 1.0000x reference)
#include <cuda_runtime.h>

// ---------------------------------------------------------------------------
// ChordProgressionLoss v6 — v5 + pm-indexed jaccard LUT + branchless loads.
//   jacLUT[4096] (smem, 32KB): pm -> packed jaccard bytes {BM, Bm} in one
//   LDS.64 (replaces 6 popc + sel-build + PRMT chain).
//   Loads clamped (min(r,T-1)) -> no BSSY/BSYNC, no zero-fill selects;
//   exactness preserved by ownership predicates on the unclamped row index.
//   Integer/fixed-point accumulators -> deterministic atomics. 296x1024.
// ---------------------------------------------------------------------------

#define NBLK 296
#define THREADS 1024
#define WPB 32

__device__ unsigned long long g_simSlots[32];
__device__ unsigned long long g_penSlots[32];
__device__ unsigned int       g_count = 0;

__device__ __forceinline__ unsigned pcbit(float f) {
    unsigned b1 = __float_as_uint(f + 12582912.0f);          // low bits = iv
    float t = fmaf(f, 0.0833333358f, -0.45833334f);
    unsigned b2 = __float_as_uint(t + 12582912.0f);          // low bits = iv/12
    unsigned x = b1 - 12u * b2;                              // low5 = iv%12
    return 1u << (x & 31u);
}
__device__ __forceinline__ unsigned pcmask(float4 v) {
    return pcbit(v.x) | pcbit(v.y) | pcbit(v.z) | pcbit(v.w);
}
// {a.b0, b.b1, c.b2, d.b3}
__device__ __forceinline__ unsigned win4(unsigned a, unsigned b, unsigned c, unsigned d) {
    unsigned p1 = __byte_perm(a, b, 0x0050);
    unsigned p2 = __byte_perm(c, d, 0x0072);
    return __byte_perm(p1, p2, 0x5410);
}

__device__ __forceinline__ void doChunk(
    float4 pv, float4 tv, int r, int T, int lane,
    const uint2* __restrict__ jacLUT, const uint2* __restrict__ sSim,
    unsigned long long& simAcc, unsigned& penAcc)
{
    unsigned pm = pcmask(pv);
    unsigned tm = pcmask(tv);
    int p  = __popc(pm);                      // 1..4
    int q  = __popc(tm);
    int it = __popc(pm & tm);

    bool own = (lane < 29) && (r < T);
    uint2 ra = sSim[p * 4 + q];
    if (own) simAcc += (unsigned long long)((unsigned)it * ra.x + ra.y);

    uint2 jb = jacLUT[pm];                    // {BM, Bm} packed bytes
    unsigned BM = jb.x, Bm = jb.y;

    unsigned M1 = __shfl_down_sync(0xffffffffu, BM, 1);
    unsigned M2 = __shfl_down_sync(0xffffffffu, BM, 2);
    unsigned M3 = __shfl_down_sync(0xffffffffu, BM, 3);
    unsigned m1 = __shfl_down_sync(0xffffffffu, Bm, 1);
    unsigned m2 = __shfl_down_sync(0xffffffffu, Bm, 2);
    unsigned m3 = __shfl_down_sync(0xffffffffu, Bm, 3);

    unsigned SM = __dp4a(win4(BM, M1, M2, M3), 0x01010101u, 0u);
    unsigned Sm = __dp4a(win4(Bm, m1, m2, m3), 0x01010101u, 0u);
    if (own && (r <= T - 4)) penAcc += (SM > Sm) ? SM : Sm;   // 240*(1-min)
}

__global__ __launch_bounds__(THREADS, 2) void chord_fused(
    const float4* __restrict__ pred, const float4* __restrict__ targ,
    float* __restrict__ out, int T, int nUnits)
{
    __shared__ uint2 jacLUT[4096];   // 32KB: pm -> {BM, Bm}
    __shared__ uint2 sSim[21];
    __shared__ unsigned long long redS[WPB], redP[WPB];
    __shared__ bool  sLast;

    const int tid = threadIdx.x;

    // fill jacLUT: bytes 60*i/(p+3-i) selected by intersection vs 6 templates
    for (int m = tid; m < 4096; m += THREADS) {
        int p = __popc(m);
        unsigned tb[4];
        #pragma unroll
        for (int i = 0; i < 4; i++) {
            int dnm = p + 3 - i;
            tb[i] = (dnm > 0) ? (unsigned)((60 * i) / dnm) : 0u;
        }
        unsigned iM0 = __popc(m & 0x091), iM1 = __popc(m & 0x221), iM2 = __popc(m & 0x884);
        unsigned im0 = __popc(m & 0x089), im1 = __popc(m & 0x121), im2 = __popc(m & 0x484);
        unsigned BM = tb[iM0] | (tb[iM1] << 8) | (tb[iM2] << 16) | (tb[iM0] << 24);
        unsigned Bm = tb[im0] | (tb[im1] << 8) | (tb[im2] << 16) | (tb[im0] << 24);
        jacLUT[m] = make_uint2(BM, Bm);
    }
    if (tid < 16) {
        int p = (tid >> 2) + 1, q = (tid & 3) + 1;
        double r = 1.0 / (((double)p + 12e-6) * ((double)q + 12e-6));
        unsigned R30 = (unsigned)__double2ll_rn(r * 1073741824.0);
        unsigned A30 = (unsigned)__double2ll_rn((1e-6 * (p + q) + 1.2e-11) * r * 1073741824.0);
        sSim[p * 4 + q] = make_uint2(R30, A30);
    }
    __syncthreads();

    const int lane = tid & 31;
    const int wid  = tid >> 5;

    unsigned long long simAcc = 0ull;
    unsigned penAcc = 0u;
    const int rMax = T - 1;

    for (int u = blockIdx.x * WPB + wid; u < nUnits; u += gridDim.x * WPB) {
        const int base = u * 58;
        const int rA = base + lane;
        const int rB = base + 29 + lane;
        const int cA = (rA < rMax) ? rA : rMax;     // clamp: branchless loads
        const int cB = (rB < rMax) ? rB : rMax;
        float4 pA = pred[cA], tA = targ[cA];        // 4x LDG.128 batched
        float4 pB = pred[cB], tB = targ[cB];

        doChunk(pA, tA, rA, T, lane, jacLUT, sSim, simAcc, penAcc);
        doChunk(pB, tB, rB, T, lane, jacLUT, sSim, simAcc, penAcc);
    }

    // warp reduction (exact integers)
    unsigned long long penW = (unsigned long long)penAcc;
    #pragma unroll
    for (int o = 16; o; o >>= 1) {
        simAcc += __shfl_xor_sync(0xffffffffu, simAcc, o);
        penW   += __shfl_xor_sync(0xffffffffu, penW,   o);
    }
    if (lane == 0) { redS[wid] = simAcc; redP[wid] = penW; }
    __syncthreads();

    if (wid == 0) {
        unsigned long long s = redS[lane];
        unsigned long long p = redP[lane];
        #pragma unroll
        for (int o = 16; o; o >>= 1) {
            s += __shfl_xor_sync(0xffffffffu, s, o);
            p += __shfl_xor_sync(0xffffffffu, p, o);
        }
        if (lane == 0) {
            int slot = blockIdx.x & 31;
            atomicAdd(&g_simSlots[slot], s);
            atomicAdd(&g_penSlots[slot], p);
            __threadfence();
            sLast = (atomicAdd(&g_count, 1u) == gridDim.x - 1);
        }
    }
    __syncthreads();

    if (sLast && wid == 0) {
        __threadfence();
        unsigned long long s = *(volatile unsigned long long*)&g_simSlots[lane];
        unsigned long long p = *(volatile unsigned long long*)&g_penSlots[lane];
        #pragma unroll
        for (int o = 16; o; o >>= 1) {
            s += __shfl_xor_sync(0xffffffffu, s, o);
            p += __shfl_xor_sync(0xffffffffu, p, o);
        }
        if (lane == 0) {
            double simMean = ((double)s * (1.0 / 1073741824.0)) / (double)T;
            long long nWin = (long long)T - 3;
            double pen = (nWin > 0) ? (0.5 - (double)p / (480.0 * (double)nWin)) : 0.0;
            out[0] = (float)((1.0 - simMean) + pen);
        }
        g_simSlots[lane] = 0ull;   // self-reset for graph replay
        g_penSlots[lane] = 0ull;
        if (lane == 0) g_count = 0;
    }
}

extern "C" void kernel_launch(void* const* d_in, const int* in_sizes, int n_in,
                              void* d_out, int out_size)
{
    const float4* pred = (const float4*)d_in[0];
    const float4* targ = (const float4*)d_in[1];
    int T1 = in_sizes[0] / 4;
    int T2 = in_sizes[1] / 4;
    int T = (T1 < T2) ? T1 : T2;

    int nUnits = (T + 57) / 58;
    if (nUnits < 1) nUnits = 1;
    int blocks = (nUnits + WPB - 1) / WPB;
    if (blocks > NBLK) blocks = NBLK;

    chord_fused<<<blocks, THREADS>>>(pred, targ, (float*)d_out, T, nUnits);
}

// round 7
// speedup vs baseline: 1.2909x; 1.2909x over previous
#include <cuda_runtime.h>

// ---------------------------------------------------------------------------
// ChordProgressionLoss v7 — R5 core (best: 14.8us) + branchless clamped
// loads (no BSSY/BSYNC, no zero-fill) + 3-shuffle P/Q byte packing (was 6).
// Jaccard bytes computed in ALU (R6 smem LUT regressed: LDS bank conflicts).
// Integer/fixed-point accumulators -> deterministic atomics. 296x1024 grid.
// ---------------------------------------------------------------------------

#define NBLK 296
#define THREADS 1024
#define WPB 32

__device__ unsigned long long g_simSlots[32];
__device__ unsigned long long g_penSlots[32];
__device__ unsigned int       g_count = 0;

__device__ __forceinline__ unsigned pcbit(float f) {
    unsigned b1 = __float_as_uint(f + 12582912.0f);          // low bits = iv
    float t = fmaf(f, 0.0833333358f, -0.45833334f);
    unsigned b2 = __float_as_uint(t + 12582912.0f);          // low bits = iv/12
    unsigned x = b1 - 12u * b2;                              // low5 = iv%12
    return 1u << (x & 31u);
}
__device__ __forceinline__ unsigned pcmask(float4 v) {
    return pcbit(v.x) | pcbit(v.y) | pcbit(v.z) | pcbit(v.w);
}

__device__ __forceinline__ void doChunk(
    float4 pv, float4 tv, int r, int T, bool laneOwn,
    const unsigned* __restrict__ sT60, const uint2* __restrict__ sSim,
    unsigned long long& simAcc, unsigned& penAcc)
{
    unsigned pm = pcmask(pv);
    unsigned tm = pcmask(tv);
    int p  = __popc(pm);                      // 1..4
    int q  = __popc(tm);
    int it = __popc(pm & tm);

    bool own = laneOwn && (r < T);
    uint2 ra = sSim[p * 4 + q];
    if (own) simAcc += (unsigned long long)((unsigned)it * ra.x + ra.y);

    unsigned Tp = sT60[p];                    // 4 jaccard bytes for this p
    unsigned iM0 = __popc(pm & 0x091u), iM1 = __popc(pm & 0x221u), iM2 = __popc(pm & 0x884u);
    unsigned im0 = __popc(pm & 0x089u), im1 = __popc(pm & 0x121u), im2 = __popc(pm & 0x484u);
    // P = {tM0, tm0, tM2, tm2};  Q = {tM1, tm1, -, -}
    unsigned selP = iM0 | (im0 << 4) | (iM2 << 8) | (im2 << 12);
    unsigned selQ = iM1 | (im1 << 4);
    unsigned P = __byte_perm(Tp, 0, selP);
    unsigned Q = __byte_perm(Tp, 0, selQ);

    unsigned Q1 = __shfl_down_sync(0xffffffffu, Q, 1);
    unsigned P2 = __shfl_down_sync(0xffffffffu, P, 2);
    unsigned P3 = __shfl_down_sync(0xffffffffu, P, 3);

    // maj window bytes {P.b0, Q1.b0, P2.b2, P3.b0}; min {P.b1, Q1.b1, P2.b3, P3.b1}
    unsigned v1 = __byte_perm(P,  Q1, 0x0040);
    unsigned v2 = __byte_perm(P2, P3, 0x0042);
    unsigned majW = __byte_perm(v1, v2, 0x5410);
    unsigned w1 = __byte_perm(P,  Q1, 0x0051);
    unsigned w2 = __byte_perm(P2, P3, 0x0053);
    unsigned minW = __byte_perm(w1, w2, 0x5410);

    unsigned SM = __dp4a(majW, 0x01010101u, 0u);
    unsigned Sm = __dp4a(minW, 0x01010101u, 0u);
    if (own && (r <= T - 4)) penAcc += (SM > Sm) ? SM : Sm;   // 240*(1-min)
}

__global__ __launch_bounds__(THREADS, 2) void chord_fused(
    const float4* __restrict__ pred, const float4* __restrict__ targ,
    float* __restrict__ out, int T, int nUnits)
{
    __shared__ unsigned sT60[5];
    __shared__ uint2    sSim[21];
    __shared__ unsigned long long redS[WPB], redP[WPB];
    __shared__ bool     sLast;

    const int tid = threadIdx.x;
    if (tid < 5) {
        int p = tid; unsigned w = 0;
        for (int i = 0; i < 4; i++) {
            int dnm = p + 3 - i;
            unsigned t = (dnm > 0) ? (unsigned)((60 * i) / dnm) : 0u;
            w |= (t & 0xFFu) << (8 * i);
        }
        sT60[p] = w;
    }
    if (tid < 16) {
        int p = (tid >> 2) + 1, q = (tid & 3) + 1;
        double r = 1.0 / (((double)p + 12e-6) * ((double)q + 12e-6));
        unsigned R30 = (unsigned)__double2ll_rn(r * 1073741824.0);
        unsigned A30 = (unsigned)__double2ll_rn((1e-6 * (p + q) + 1.2e-11) * r * 1073741824.0);
        sSim[p * 4 + q] = make_uint2(R30, A30);
    }
    __syncthreads();

    const int lane = tid & 31;
    const int wid  = tid >> 5;
    const bool laneOwn = (lane < 29);

    unsigned long long simAcc = 0ull;
    unsigned penAcc = 0u;
    const int rMax = (T > 0) ? (T - 1) : 0;

    for (int u = blockIdx.x * WPB + wid; u < nUnits; u += gridDim.x * WPB) {
        const int base = u * 58;
        const int rA = base + lane;
        const int rB = base + 29 + lane;
        const int cA = (rA < rMax) ? rA : rMax;     // clamp: branchless loads
        const int cB = (rB < rMax) ? rB : rMax;
        float4 pA = pred[cA], tA = targ[cA];        // 4x LDG.128 batched
        float4 pB = pred[cB], tB = targ[cB];

        doChunk(pA, tA, rA, T, laneOwn, sT60, sSim, simAcc, penAcc);
        doChunk(pB, tB, rB, T, laneOwn, sT60, sSim, simAcc, penAcc);
    }

    // warp reduction (exact integers -> order-independent)
    unsigned long long penW = (unsigned long long)penAcc;
    #pragma unroll
    for (int o = 16; o; o >>= 1) {
        simAcc += __shfl_xor_sync(0xffffffffu, simAcc, o);
        penW   += __shfl_xor_sync(0xffffffffu, penW,   o);
    }
    if (lane == 0) { redS[wid] = simAcc; redP[wid] = penW; }
    __syncthreads();

    if (wid == 0) {
        unsigned long long s = redS[lane];
        unsigned long long p = redP[lane];
        #pragma unroll
        for (int o = 16; o; o >>= 1) {
            s += __shfl_xor_sync(0xffffffffu, s, o);
            p += __shfl_xor_sync(0xffffffffu, p, o);
        }
        if (lane == 0) {
            int slot = blockIdx.x & 31;
            atomicAdd(&g_simSlots[slot], s);
            atomicAdd(&g_penSlots[slot], p);
            __threadfence();
            sLast = (atomicAdd(&g_count, 1u) == gridDim.x - 1);
        }
    }
    __syncthreads();

    if (sLast && wid == 0) {
        __threadfence();
        unsigned long long s = *(volatile unsigned long long*)&g_simSlots[lane];
        unsigned long long p = *(volatile unsigned long long*)&g_penSlots[lane];
        #pragma unroll
        for (int o = 16; o; o >>= 1) {
            s += __shfl_xor_sync(0xffffffffu, s, o);
            p += __shfl_xor_sync(0xffffffffu, p, o);
        }
        if (lane == 0) {
            double simMean = ((double)s * (1.0 / 1073741824.0)) / (double)T;
            long long nWin = (long long)T - 3;
            double pen = (nWin > 0) ? (0.5 - (double)p / (480.0 * (double)nWin)) : 0.0;
            out[0] = (float)((1.0 - simMean) + pen);
        }
        g_simSlots[lane] = 0ull;   // self-reset for graph replay
        g_penSlots[lane] = 0ull;
        if (lane == 0) g_count = 0;
    }
}

extern "C" void kernel_launch(void* const* d_in, const int* in_sizes, int n_in,
                              void* d_out, int out_size)
{
    const float4* pred = (const float4*)d_in[0];
    const float4* targ = (const float4*)d_in[1];
    int T1 = in_sizes[0] / 4;
    int T2 = in_sizes[1] / 4;
    int T = (T1 < T2) ? T1 : T2;

    int nUnits = (T + 57) / 58;
    if (nUnits < 1) nUnits = 1;
    int blocks = (nUnits + WPB - 1) / WPB;
    if (blocks > NBLK) blocks = NBLK;

    chord_fused<<<blocks, THREADS>>>(pred, targ, (float*)d_out, T, nUnits);
}